// round 15
// baseline (speedup 1.0000x reference)
#include <cuda_runtime.h>
#include <cuda_bf16.h>
#include <math.h>

// ---------------- constants ----------------
#define BB    4
#define SQ    1024
#define SKV   512
#define DD    2048
#define KDIM  1024
#define HH    16
#define HD    128
#define INTER 8192
#define RNK   16
#define NATTN 3
#define MQ    (BB*SQ)     // 4096
#define MKV   (BB*SKV)    // 2048
#define ATTN_SCALE 0.08838834764831845f  // 1/sqrt(128)
#define LORA_SCALE 2.0f                  // 32/16
#define EPSV 1e-6f

// ---------------- device scratch ----------------
__device__ float g_rrms[MQ];
__device__ float g_qpool[BB*DD];
__device__ float g_wattn[NATTN*BB];            // [e][b]
__device__ float g_Q[MQ*DD];
__device__ float g_K[MKV*DD];
__device__ float g_V[MKV*DD];
__device__ float g_S[(size_t)BB*HH*SQ*SKV];    // 32M floats
__device__ float g_O[MQ*DD];
__device__ float g_delta[MQ*DD];
__device__ float g_xf[MQ*DD];
__device__ float g_h[MQ*DD];
__device__ float g_G[(size_t)MQ*INTER];        // also reused as d_in (in-place)
__device__ float g_U[(size_t)MQ*INTER];
__device__ float g_mlp[MQ*DD];
__device__ float g_tG[MQ*RNK];
__device__ float g_tU[MQ*RNK];
__device__ float g_tD[MQ*RNK];

__device__ __forceinline__ float4 ldg4(const float* p) {
    return *reinterpret_cast<const float4*>(p);
}

// ---------------- generic SGEMM 128x128x16, 256 threads, 8x8 micro ----------------
// C = epilogue( A @ B(^T) ), row-major, all dims multiples of tile sizes.
// Batched via blockIdx.z with two-level offset: b1 = z/bdiv, b2 = z%bdiv.
// gate: if non-null, block reads gate[gb]; returns if 0. gb from z (batched) or
// from m-tile (rows-per-batch). GMUL multiplies result by gate weight (Wo combine).
template<bool TRANSB, bool ACCUM, bool GMUL>
__global__ __launch_bounds__(256)
void sgemm_k(const float* __restrict__ A, int lda, long long sA1, long long sA2,
             const float* __restrict__ Bm, int ldb, long long sB1, long long sB2,
             float* __restrict__ C, int ldc, long long sC1, long long sC2,
             int K,
             const float* __restrict__ bias,
             float alpha,
             const float* __restrict__ gate, int gate_zdiv, int gate_rows,
             int bdiv)
{
    const int bz = blockIdx.z;
    float w = 1.f;
    if (gate) {
        int gb;
        if (gridDim.z > 1) gb = bz / gate_zdiv;
        else               gb = (blockIdx.y * 128) / gate_rows;
        w = gate[gb];
        if (w == 0.f) return;
    }
    const int b1 = bz / bdiv, b2 = bz % bdiv;
    A  += (long long)b1*sA1 + (long long)b2*sA2;
    Bm += (long long)b1*sB1 + (long long)b2*sB2;
    C  += (long long)b1*sC1 + (long long)b2*sC2;

    const int m0 = blockIdx.y * 128;
    const int n0 = blockIdx.x * 128;
    const int tid = threadIdx.x;
    const int tm = tid >> 4;    // 0..15
    const int tn = tid & 15;    // 0..15

    __shared__ float As[16*128];
    __shared__ float Bs[16*128];

    float acc[8][8];
    #pragma unroll
    for (int i = 0; i < 8; i++)
        #pragma unroll
        for (int j = 0; j < 8; j++) acc[i][j] = 0.f;

    for (int k0 = 0; k0 < K; k0 += 16) {
        // A tile: 128 rows x 16 k
        #pragma unroll
        for (int i = 0; i < 2; i++) {
            int idx = i*256 + tid;
            int r = idx >> 2;
            int c4 = idx & 3;
            float4 v = ldg4(A + (size_t)(m0 + r)*lda + k0 + c4*4);
            As[(c4*4+0)*128 + r] = v.x;
            As[(c4*4+1)*128 + r] = v.y;
            As[(c4*4+2)*128 + r] = v.z;
            As[(c4*4+3)*128 + r] = v.w;
        }
        if (TRANSB) {
            // B is [N, ldb]; need Bs[k][n] = B[n0+n][k0+k]
            #pragma unroll
            for (int i = 0; i < 2; i++) {
                int idx = i*256 + tid;
                int r = idx >> 2;     // n
                int c4 = idx & 3;
                float4 v = ldg4(Bm + (size_t)(n0 + r)*ldb + k0 + c4*4);
                Bs[(c4*4+0)*128 + r] = v.x;
                Bs[(c4*4+1)*128 + r] = v.y;
                Bs[(c4*4+2)*128 + r] = v.z;
                Bs[(c4*4+3)*128 + r] = v.w;
            }
        } else {
            // B is [K, ldb]; Bs[k][n] direct
            #pragma unroll
            for (int i = 0; i < 2; i++) {
                int idx = i*256 + tid;
                int r = idx >> 5;     // k row 0..15
                int c4 = idx & 31;    // 0..31
                float4 v = ldg4(Bm + (size_t)(k0 + r)*ldb + n0 + c4*4);
                *reinterpret_cast<float4*>(&Bs[r*128 + c4*4]) = v;
            }
        }
        __syncthreads();
        #pragma unroll
        for (int kk = 0; kk < 16; kk++) {
            float a[8], b[8];
            *reinterpret_cast<float4*>(a)   = *reinterpret_cast<float4*>(&As[kk*128 + tm*8]);
            *reinterpret_cast<float4*>(a+4) = *reinterpret_cast<float4*>(&As[kk*128 + tm*8 + 4]);
            *reinterpret_cast<float4*>(b)   = *reinterpret_cast<float4*>(&Bs[kk*128 + tn*8]);
            *reinterpret_cast<float4*>(b+4) = *reinterpret_cast<float4*>(&Bs[kk*128 + tn*8 + 4]);
            #pragma unroll
            for (int i = 0; i < 8; i++)
                #pragma unroll
                for (int j = 0; j < 8; j++)
                    acc[i][j] += a[i]*b[j];
        }
        __syncthreads();
    }

    float bb[8];
    #pragma unroll
    for (int j = 0; j < 8; j++)
        bb[j] = bias ? bias[n0 + tn*8 + j] : 0.f;

    #pragma unroll
    for (int i = 0; i < 8; i++) {
        float* crow = C + (size_t)(m0 + tm*8 + i)*ldc + n0 + tn*8;
        #pragma unroll
        for (int j = 0; j < 8; j++) {
            float r = (acc[i][j] + bb[j]) * alpha;
            if (GMUL) r *= w;
            if (ACCUM) r += crow[j];
            crow[j] = r;
        }
    }
}

// ---------------- small kernels ----------------

// per-row 1/rms of x_q (for router pooling)
__global__ void row_rrms_k(const float* __restrict__ x, float* __restrict__ rrms) {
    int m = blockIdx.x;
    int tid = threadIdx.x;
    const float* row = x + (size_t)m * DD;
    float s = 0.f;
    for (int i = tid; i < DD; i += 256) { float v = row[i]; s += v*v; }
    __shared__ float red[256];
    red[tid] = s; __syncthreads();
    for (int o = 128; o > 0; o >>= 1) { if (tid < o) red[tid] += red[tid+o]; __syncthreads(); }
    if (tid == 0) rrms[m] = rsqrtf(red[0] * (1.f/DD) + EPSV);
}

// q_pool[b,d] = ln1[d] * mean_s( x[b,s,d]*rrms[b,s] )
__global__ void pool_k(const float* __restrict__ x, const float* __restrict__ rrms,
                       const float* __restrict__ ln1, float* __restrict__ qpool) {
    int d = blockIdx.x*256 + threadIdx.x;
    int b = blockIdx.y;
    const float* xb = x + (size_t)b*SQ*DD;
    const float* rb = rrms + b*SQ;
    float s = 0.f;
    for (int t = 0; t < SQ; t++) s += xb[(size_t)t*DD + d] * rb[t];
    qpool[b*DD + d] = ln1[d] * s * (1.f/SQ);
}

// router: softmax -> top2 -> renorm -> dense weights for 3 attention experts
__global__ void router_k(const float* __restrict__ qpool, const float* __restrict__ W,
                         const float* __restrict__ rb, float* __restrict__ wattn) {
    int warp = threadIdx.x >> 5, lane = threadIdx.x & 31;
    if (warp >= BB) return;
    float lg[4];
    #pragma unroll
    for (int e = 0; e < 4; e++) {
        float s = 0.f;
        for (int d = lane; d < DD; d += 32) s += qpool[warp*DD + d] * W[d*4 + e];
        #pragma unroll
        for (int o = 16; o > 0; o >>= 1) s += __shfl_down_sync(0xffffffffu, s, o);
        lg[e] = s;
    }
    if (lane == 0) {
        float p[4];
        float mx = -1e30f;
        #pragma unroll
        for (int e = 0; e < 4; e++) { lg[e] += rb[e]; mx = fmaxf(mx, lg[e]); }
        float sum = 0.f;
        #pragma unroll
        for (int e = 0; e < 4; e++) { p[e] = expf(lg[e]-mx); sum += p[e]; }
        #pragma unroll
        for (int e = 0; e < 4; e++) p[e] /= sum;
        int i1 = 0;
        for (int e = 1; e < 4; e++) if (p[e] > p[i1]) i1 = e;
        int i2 = -1;
        for (int e = 0; e < 4; e++) if (e != i1 && (i2 < 0 || p[e] > p[i2])) i2 = e;
        float s2 = p[i1] + p[i2] + 1e-10f;
        for (int e = 0; e < NATTN; e++) {
            float wv = 0.f;
            if (e == i1) wv = p[i1]/s2; else if (e == i2) wv = p[i2]/s2;
            wattn[e*BB + warp] = wv;
        }
    }
}

__global__ void zero_k(float* __restrict__ p, int n) {
    int i = blockIdx.x*256 + threadIdx.x;
    if (i < n) p[i] = 0.f;
}

// softmax over rows of 512, gated per batch
__global__ void softmax_k(float* __restrict__ S, const float* __restrict__ gate,
                          int rows_per_gate) {
    long long row = blockIdx.x;
    if (gate[row / rows_per_gate] == 0.f) return;
    float* p = S + row*SKV;
    int tid = threadIdx.x;  // 128
    float v[4];
    float mx = -1e30f;
    #pragma unroll
    for (int i = 0; i < 4; i++) { v[i] = p[tid + i*128]; mx = fmaxf(mx, v[i]); }
    __shared__ float red[128];
    red[tid] = mx; __syncthreads();
    for (int o = 64; o > 0; o >>= 1) { if (tid < o) red[tid] = fmaxf(red[tid], red[tid+o]); __syncthreads(); }
    mx = red[0]; __syncthreads();
    float s = 0.f;
    #pragma unroll
    for (int i = 0; i < 4; i++) { v[i] = expf(v[i]-mx); s += v[i]; }
    red[tid] = s; __syncthreads();
    for (int o = 64; o > 0; o >>= 1) { if (tid < o) red[tid] += red[tid+o]; __syncthreads(); }
    float inv = 1.f / red[0];
    #pragma unroll
    for (int i = 0; i < 4; i++) p[tid + i*128] = v[i]*inv;
}

// x_f = x_q + sigmoid(a1)*delta; h = rmsnorm(x_f, ln2)
__global__ void xf_rms_k(const float* __restrict__ xq, const float* __restrict__ delta,
                         const float* __restrict__ a1, const float* __restrict__ ln2,
                         float* __restrict__ xf, float* __restrict__ hout) {
    int m = blockIdx.x;
    int tid = threadIdx.x;  // 256
    float sig = 1.f/(1.f + expf(-a1[0]));
    const size_t base = (size_t)m*DD;
    float vals[8];
    float s = 0.f;
    #pragma unroll
    for (int i = 0; i < 8; i++) {
        int d = tid + i*256;
        float v = xq[base+d] + sig*delta[base+d];
        vals[i] = v; s += v*v;
    }
    __shared__ float red[256];
    red[tid] = s; __syncthreads();
    for (int o = 128; o > 0; o >>= 1) { if (tid < o) red[tid] += red[tid+o]; __syncthreads(); }
    float rr = rsqrtf(red[0] * (1.f/DD) + EPSV);
    #pragma unroll
    for (int i = 0; i < 8; i++) {
        int d = tid + i*256;
        xf[base+d]  = vals[i];
        hout[base+d] = ln2[d] * vals[i] * rr;
    }
}

// T1[m,r] = sum_d H[m,d]*A1[d,r]  (+ optionally T2 with A2); rank 16, 16 warps
__global__ void lora16_k(const float* __restrict__ Hm, const float* __restrict__ A1,
                         const float* __restrict__ A2, float* __restrict__ T1,
                         float* __restrict__ T2, int Kd) {
    extern __shared__ float hrow[];
    int m = blockIdx.x;
    for (int i = threadIdx.x; i < Kd; i += blockDim.x) hrow[i] = Hm[(size_t)m*Kd + i];
    __syncthreads();
    int w = threadIdx.x >> 5, lane = threadIdx.x & 31;
    float s1 = 0.f, s2 = 0.f;
    for (int d = lane; d < Kd; d += 32) {
        float hv = hrow[d];
        s1 += hv * A1[d*RNK + w];
        if (A2) s2 += hv * A2[d*RNK + w];
    }
    #pragma unroll
    for (int o = 16; o > 0; o >>= 1) {
        s1 += __shfl_down_sync(0xffffffffu, s1, o);
        s2 += __shfl_down_sync(0xffffffffu, s2, o);
    }
    if (lane == 0) {
        T1[m*RNK + w] = s1;
        if (A2) T2[m*RNK + w] = s2;
    }
}

// d_in = silu(G + sc*tG@lgB) + (U + sc*tU@luB), written in place over G
__global__ void combine_k(float* __restrict__ G, const float* __restrict__ U,
                          const float* __restrict__ tG, const float* __restrict__ tU,
                          const float* __restrict__ lgB, const float* __restrict__ luB) {
    int m = blockIdx.y;
    int n = blockIdx.x*256 + threadIdx.x;
    __shared__ float sg[RNK], su[RNK];
    if (threadIdx.x < RNK) sg[threadIdx.x] = tG[m*RNK + threadIdx.x];
    else if (threadIdx.x < 2*RNK) su[threadIdx.x - RNK] = tU[m*RNK + threadIdx.x - RNK];
    __syncthreads();
    size_t idx = (size_t)m*INTER + n;
    float g = G[idx], u = U[idx];
    #pragma unroll
    for (int r = 0; r < RNK; r++) {
        g += LORA_SCALE * sg[r] * lgB[r*INTER + n];
        u += LORA_SCALE * su[r] * luB[r*INTER + n];
    }
    float silu = g / (1.f + expf(-g));
    G[idx] = silu + u;
}

// out = x_f + sigmoid(a2)*(mlp + sc*tD@ldB)
__global__ void final_k(const float* __restrict__ xf, const float* __restrict__ mlp,
                        const float* __restrict__ tD, const float* __restrict__ ldB,
                        const float* __restrict__ a2, float* __restrict__ out) {
    int m = blockIdx.y;
    int n = blockIdx.x*256 + threadIdx.x;
    __shared__ float sd[RNK];
    if (threadIdx.x < RNK) sd[threadIdx.x] = tD[m*RNK + threadIdx.x];
    __syncthreads();
    float sig = 1.f/(1.f + expf(-a2[0]));
    size_t idx = (size_t)m*DD + n;
    float r = mlp[idx];
    #pragma unroll
    for (int k = 0; k < RNK; k++) r += LORA_SCALE * sd[k] * ldB[k*DD + n];
    out[idx] = xf[idx] + sig*r;
}

// ---------------- host launch ----------------
extern "C" void kernel_launch(void* const* d_in, const int* in_sizes, int n_in,
                              void* d_out, int out_size) {
    const float* x_q      = (const float*)d_in[0];
    const float* z_a      = (const float*)d_in[1];
    const float* z_v      = (const float*)d_in[2];
    const float* z_av     = (const float*)d_in[3];
    const float* ln1_w    = (const float*)d_in[4];
    const float* ln2_w    = (const float*)d_in[5];
    const float* router_W = (const float*)d_in[6];
    const float* router_b = (const float*)d_in[7];
    const float* Wq       = (const float*)d_in[8];
    const float* bq       = (const float*)d_in[9];
    const float* Wk       = (const float*)d_in[10];
    const float* bk       = (const float*)d_in[11];
    const float* Wv       = (const float*)d_in[12];
    const float* bv       = (const float*)d_in[13];
    const float* Wo       = (const float*)d_in[14];
    const float* bo       = (const float*)d_in[15];
    const float* gate_W   = (const float*)d_in[16];
    const float* up_W     = (const float*)d_in[17];
    const float* down_W   = (const float*)d_in[18];
    const float* lg_A     = (const float*)d_in[19];
    const float* lg_B     = (const float*)d_in[20];
    const float* lu_A     = (const float*)d_in[21];
    const float* lu_B     = (const float*)d_in[22];
    const float* ld_A     = (const float*)d_in[23];
    const float* ld_B     = (const float*)d_in[24];
    const float* alpha_1  = (const float*)d_in[25];
    const float* alpha_2  = (const float*)d_in[26];
    float* out = (float*)d_out;

    float *Qb,*Kb,*Vb,*Sb,*Ob,*Delta,*Xf,*Hb,*Gb,*Ub,*Mlp,*rrms,*qpool,*wattn,*tG,*tU,*tD;
    cudaGetSymbolAddress((void**)&Qb,    g_Q);
    cudaGetSymbolAddress((void**)&Kb,    g_K);
    cudaGetSymbolAddress((void**)&Vb,    g_V);
    cudaGetSymbolAddress((void**)&Sb,    g_S);
    cudaGetSymbolAddress((void**)&Ob,    g_O);
    cudaGetSymbolAddress((void**)&Delta, g_delta);
    cudaGetSymbolAddress((void**)&Xf,    g_xf);
    cudaGetSymbolAddress((void**)&Hb,    g_h);
    cudaGetSymbolAddress((void**)&Gb,    g_G);
    cudaGetSymbolAddress((void**)&Ub,    g_U);
    cudaGetSymbolAddress((void**)&Mlp,   g_mlp);
    cudaGetSymbolAddress((void**)&rrms,  g_rrms);
    cudaGetSymbolAddress((void**)&qpool, g_qpool);
    cudaGetSymbolAddress((void**)&wattn, g_wattn);
    cudaGetSymbolAddress((void**)&tG,    g_tG);
    cudaGetSymbolAddress((void**)&tU,    g_tU);
    cudaGetSymbolAddress((void**)&tD,    g_tD);

    // ---- router ----
    row_rrms_k<<<MQ, 256>>>(x_q, rrms);
    pool_k<<<dim3(DD/256, BB), 256>>>(x_q, rrms, ln1_w, qpool);
    router_k<<<1, 128>>>(qpool, router_W, router_b, wattn);
    zero_k<<<(MQ*DD)/256, 256>>>(Delta, MQ*DD);

    // ---- experts ----
    const float* zs[3] = { z_a, z_v, z_av };
    for (int e = 0; e < NATTN; e++) {
        const float* gate = wattn + e*BB;
        // Q = x_q @ Wq[e] + bq[e]   [4096,2048]
        sgemm_k<false,false,false><<<dim3(DD/128, MQ/128, 1), 256>>>(
            x_q, DD, 0, 0, Wq + (size_t)e*DD*DD, DD, 0, 0,
            Qb, DD, 0, 0, DD, bq + e*DD, 1.f, gate, 1, SQ, 1);
        // K = z_e @ Wk[e] + bk[e]   [2048,2048]
        sgemm_k<false,false,false><<<dim3(DD/128, MKV/128, 1), 256>>>(
            zs[e], KDIM, 0, 0, Wk + (size_t)e*KDIM*DD, DD, 0, 0,
            Kb, DD, 0, 0, KDIM, bk + e*DD, 1.f, gate, 1, SKV, 1);
        // V = z_e @ Wv[e] + bv[e]
        sgemm_k<false,false,false><<<dim3(DD/128, MKV/128, 1), 256>>>(
            zs[e], KDIM, 0, 0, Wv + (size_t)e*KDIM*DD, DD, 0, 0,
            Vb, DD, 0, 0, KDIM, bv + e*DD, 1.f, gate, 1, SKV, 1);
        // scores[b,h] = scale * Q[b,:,h,:] @ K[b,:,h,:]^T   (batched over 64)
        sgemm_k<true,false,false><<<dim3(SKV/128, SQ/128, BB*HH), 256>>>(
            Qb, DD, (long long)SQ*DD, HD,
            Kb, DD, (long long)SKV*DD, HD,
            Sb, SKV, (long long)HH*SQ*SKV, (long long)SQ*SKV,
            HD, nullptr, ATTN_SCALE, gate, HH, 0, HH);
        // softmax
        softmax_k<<<BB*HH*SQ, 128>>>(Sb, gate, HH*SQ);
        // O[b,:,h,:] = P @ V[b,:,h,:]
        sgemm_k<false,false,false><<<dim3(HD/128, SQ/128, BB*HH), 256>>>(
            Sb, SKV, (long long)HH*SQ*SKV, (long long)SQ*SKV,
            Vb, DD, (long long)SKV*DD, HD,
            Ob, DD, (long long)SQ*DD, HD,
            SKV, nullptr, 1.f, gate, HH, 0, HH);
        // delta += w[b,e] * (O @ Wo[e] + bo[e])
        sgemm_k<false,true,true><<<dim3(DD/128, MQ/128, 1), 256>>>(
            Ob, DD, 0, 0, Wo + (size_t)e*DD*DD, DD, 0, 0,
            Delta, DD, 0, 0, DD, bo + e*DD, 1.f, gate, 1, SQ, 1);
    }

    // ---- MLP ----
    xf_rms_k<<<MQ, 256>>>(x_q, Delta, alpha_1, ln2_w, Xf, Hb);
    lora16_k<<<MQ, 512, DD*sizeof(float)>>>(Hb, lg_A, lu_A, tG, tU, DD);
    sgemm_k<false,false,false><<<dim3(INTER/128, MQ/128, 1), 256>>>(
        Hb, DD, 0, 0, gate_W, INTER, 0, 0, Gb, INTER, 0, 0,
        DD, nullptr, 1.f, nullptr, 1, 1, 1);
    sgemm_k<false,false,false><<<dim3(INTER/128, MQ/128, 1), 256>>>(
        Hb, DD, 0, 0, up_W, INTER, 0, 0, Ub, INTER, 0, 0,
        DD, nullptr, 1.f, nullptr, 1, 1, 1);
    combine_k<<<dim3(INTER/256, MQ), 256>>>(Gb, Ub, tG, tU, lg_B, lu_B);
    lora16_k<<<MQ, 512, INTER*sizeof(float)>>>(Gb, ld_A, nullptr, tD, nullptr, INTER);
    sgemm_k<false,false,false><<<dim3(DD/128, MQ/128, 1), 256>>>(
        Gb, INTER, 0, 0, down_W, DD, 0, 0, Mlp, DD, 0, 0,
        INTER, nullptr, 1.f, nullptr, 1, 1, 1);
    final_k<<<dim3(DD/256, MQ), 256>>>(Xf, Mlp, tD, ld_B, alpha_2, out);
}

// round 16
// speedup vs baseline: 1.0129x; 1.0129x over previous
#include <cuda_runtime.h>
#include <cuda_bf16.h>
#include <math.h>

// ---------------- constants ----------------
#define BB    4
#define SQ    1024
#define SKV   512
#define DD    2048
#define KDIM  1024
#define HH    16
#define HD    128
#define INTER 8192
#define RNK   16
#define NATTN 3
#define MQ    (BB*SQ)     // 4096
#define MKV   (BB*SKV)    // 2048
#define ATTN_SCALE 0.08838834764831845f  // 1/sqrt(128)
#define LORA_SCALE 2.0f                  // 32/16
#define EPSV 1e-6f

// ---------------- device scratch ----------------
__device__ float g_rrms[MQ];
__device__ float g_qpool[BB*DD];
__device__ float g_wattn[NATTN*BB];            // [e][b]
__device__ float g_Q[MQ*DD];
__device__ float g_K[MKV*DD];
__device__ float g_V[MKV*DD];
__device__ float g_S[(size_t)BB*HH*SQ*SKV];    // 32M floats
__device__ float g_O[MQ*DD];
__device__ float g_delta[MQ*DD];
__device__ float g_xf[MQ*DD];
__device__ float g_h[MQ*DD];
__device__ float g_G[(size_t)MQ*INTER];        // also reused as d_in (in-place)
__device__ float g_U[(size_t)MQ*INTER];
__device__ float g_mlp[MQ*DD];
__device__ float g_tG[MQ*RNK];
__device__ float g_tU[MQ*RNK];
__device__ float g_tD[MQ*RNK];

__device__ __forceinline__ float4 ldg4(const float* p) {
    return *reinterpret_cast<const float4*>(p);
}

// ---------------- generic SGEMM 128x128x16, 256 threads, 8x8 micro ----------------
// C = epilogue( A @ B(^T) ), row-major, all dims multiples of tile sizes.
// Batched via blockIdx.z with two-level offset: b1 = z/bdiv, b2 = z%bdiv.
// gate: if non-null, block reads gate[gb]; returns if 0. gb from z (batched) or
// from m-tile (rows-per-batch). GMUL multiplies result by gate weight (Wo combine).
template<bool TRANSB, bool ACCUM, bool GMUL>
__global__ __launch_bounds__(256)
void sgemm_k(const float* __restrict__ A, int lda, long long sA1, long long sA2,
             const float* __restrict__ Bm, int ldb, long long sB1, long long sB2,
             float* __restrict__ C, int ldc, long long sC1, long long sC2,
             int K,
             const float* __restrict__ bias,
             float alpha,
             const float* __restrict__ gate, int gate_zdiv, int gate_rows,
             int bdiv)
{
    const int bz = blockIdx.z;
    float w = 1.f;
    if (gate) {
        int gb;
        if (gridDim.z > 1) gb = bz / gate_zdiv;
        else               gb = (blockIdx.y * 128) / gate_rows;
        w = gate[gb];
        if (w == 0.f) return;
    }
    const int b1 = bz / bdiv, b2 = bz % bdiv;
    A  += (long long)b1*sA1 + (long long)b2*sA2;
    Bm += (long long)b1*sB1 + (long long)b2*sB2;
    C  += (long long)b1*sC1 + (long long)b2*sC2;

    const int m0 = blockIdx.y * 128;
    const int n0 = blockIdx.x * 128;
    const int tid = threadIdx.x;
    const int tm = tid >> 4;    // 0..15
    const int tn = tid & 15;    // 0..15

    __shared__ float As[16*128];
    __shared__ float Bs[16*128];

    float acc[8][8];
    #pragma unroll
    for (int i = 0; i < 8; i++)
        #pragma unroll
        for (int j = 0; j < 8; j++) acc[i][j] = 0.f;

    for (int k0 = 0; k0 < K; k0 += 16) {
        // A tile: 128 rows x 16 k
        #pragma unroll
        for (int i = 0; i < 2; i++) {
            int idx = i*256 + tid;
            int r = idx >> 2;
            int c4 = idx & 3;
            float4 v = ldg4(A + (size_t)(m0 + r)*lda + k0 + c4*4);
            As[(c4*4+0)*128 + r] = v.x;
            As[(c4*4+1)*128 + r] = v.y;
            As[(c4*4+2)*128 + r] = v.z;
            As[(c4*4+3)*128 + r] = v.w;
        }
        if (TRANSB) {
            // B is [N, ldb]; need Bs[k][n] = B[n0+n][k0+k]
            #pragma unroll
            for (int i = 0; i < 2; i++) {
                int idx = i*256 + tid;
                int r = idx >> 2;     // n
                int c4 = idx & 3;
                float4 v = ldg4(Bm + (size_t)(n0 + r)*ldb + k0 + c4*4);
                Bs[(c4*4+0)*128 + r] = v.x;
                Bs[(c4*4+1)*128 + r] = v.y;
                Bs[(c4*4+2)*128 + r] = v.z;
                Bs[(c4*4+3)*128 + r] = v.w;
            }
        } else {
            // B is [K, ldb]; Bs[k][n] direct
            #pragma unroll
            for (int i = 0; i < 2; i++) {
                int idx = i*256 + tid;
                int r = idx >> 5;     // k row 0..15
                int c4 = idx & 31;    // 0..31
                float4 v = ldg4(Bm + (size_t)(k0 + r)*ldb + n0 + c4*4);
                *reinterpret_cast<float4*>(&Bs[r*128 + c4*4]) = v;
            }
        }
        __syncthreads();
        #pragma unroll
        for (int kk = 0; kk < 16; kk++) {
            float a[8], b[8];
            *reinterpret_cast<float4*>(a)   = *reinterpret_cast<float4*>(&As[kk*128 + tm*8]);
            *reinterpret_cast<float4*>(a+4) = *reinterpret_cast<float4*>(&As[kk*128 + tm*8 + 4]);
            *reinterpret_cast<float4*>(b)   = *reinterpret_cast<float4*>(&Bs[kk*128 + tn*8]);
            *reinterpret_cast<float4*>(b+4) = *reinterpret_cast<float4*>(&Bs[kk*128 + tn*8 + 4]);
            #pragma unroll
            for (int i = 0; i < 8; i++)
                #pragma unroll
                for (int j = 0; j < 8; j++)
                    acc[i][j] += a[i]*b[j];
        }
        __syncthreads();
    }

    float bb[8];
    #pragma unroll
    for (int j = 0; j < 8; j++)
        bb[j] = bias ? bias[n0 + tn*8 + j] : 0.f;

    #pragma unroll
    for (int i = 0; i < 8; i++) {
        float* crow = C + (size_t)(m0 + tm*8 + i)*ldc + n0 + tn*8;
        #pragma unroll
        for (int j = 0; j < 8; j++) {
            float r = (acc[i][j] + bb[j]) * alpha;
            if (GMUL) r *= w;
            if (ACCUM) r += crow[j];
            crow[j] = r;
        }
    }
}

// ---------------- small kernels ----------------

// per-row 1/rms of x_q (for router pooling)
__global__ void row_rrms_k(const float* __restrict__ x, float* __restrict__ rrms) {
    int m = blockIdx.x;
    int tid = threadIdx.x;
    const float* row = x + (size_t)m * DD;
    float s = 0.f;
    for (int i = tid; i < DD; i += 256) { float v = row[i]; s += v*v; }
    __shared__ float red[256];
    red[tid] = s; __syncthreads();
    for (int o = 128; o > 0; o >>= 1) { if (tid < o) red[tid] += red[tid+o]; __syncthreads(); }
    if (tid == 0) rrms[m] = rsqrtf(red[0] * (1.f/DD) + EPSV);
}

// q_pool[b,d] = ln1[d] * mean_s( x[b,s,d]*rrms[b,s] )
__global__ void pool_k(const float* __restrict__ x, const float* __restrict__ rrms,
                       const float* __restrict__ ln1, float* __restrict__ qpool) {
    int d = blockIdx.x*256 + threadIdx.x;
    int b = blockIdx.y;
    const float* xb = x + (size_t)b*SQ*DD;
    const float* rb = rrms + b*SQ;
    float s = 0.f;
    for (int t = 0; t < SQ; t++) s += xb[(size_t)t*DD + d] * rb[t];
    qpool[b*DD + d] = ln1[d] * s * (1.f/SQ);
}

// router: softmax -> top2 -> renorm -> dense weights for 3 attention experts
__global__ void router_k(const float* __restrict__ qpool, const float* __restrict__ W,
                         const float* __restrict__ rb, float* __restrict__ wattn) {
    int warp = threadIdx.x >> 5, lane = threadIdx.x & 31;
    if (warp >= BB) return;
    float lg[4];
    #pragma unroll
    for (int e = 0; e < 4; e++) {
        float s = 0.f;
        for (int d = lane; d < DD; d += 32) s += qpool[warp*DD + d] * W[d*4 + e];
        #pragma unroll
        for (int o = 16; o > 0; o >>= 1) s += __shfl_down_sync(0xffffffffu, s, o);
        lg[e] = s;
    }
    if (lane == 0) {
        float p[4];
        float mx = -1e30f;
        #pragma unroll
        for (int e = 0; e < 4; e++) { lg[e] += rb[e]; mx = fmaxf(mx, lg[e]); }
        float sum = 0.f;
        #pragma unroll
        for (int e = 0; e < 4; e++) { p[e] = expf(lg[e]-mx); sum += p[e]; }
        #pragma unroll
        for (int e = 0; e < 4; e++) p[e] /= sum;
        int i1 = 0;
        for (int e = 1; e < 4; e++) if (p[e] > p[i1]) i1 = e;
        int i2 = -1;
        for (int e = 0; e < 4; e++) if (e != i1 && (i2 < 0 || p[e] > p[i2])) i2 = e;
        float s2 = p[i1] + p[i2] + 1e-10f;
        for (int e = 0; e < NATTN; e++) {
            float wv = 0.f;
            if (e == i1) wv = p[i1]/s2; else if (e == i2) wv = p[i2]/s2;
            wattn[e*BB + warp] = wv;
        }
    }
}

__global__ void zero_k(float* __restrict__ p, int n) {
    int i = blockIdx.x*256 + threadIdx.x;
    if (i < n) p[i] = 0.f;
}

// softmax over rows of 512, gated per batch
__global__ void softmax_k(float* __restrict__ S, const float* __restrict__ gate,
                          int rows_per_gate) {
    long long row = blockIdx.x;
    if (gate[row / rows_per_gate] == 0.f) return;
    float* p = S + row*SKV;
    int tid = threadIdx.x;  // 128
    float v[4];
    float mx = -1e30f;
    #pragma unroll
    for (int i = 0; i < 4; i++) { v[i] = p[tid + i*128]; mx = fmaxf(mx, v[i]); }
    __shared__ float red[128];
    red[tid] = mx; __syncthreads();
    for (int o = 64; o > 0; o >>= 1) { if (tid < o) red[tid] = fmaxf(red[tid], red[tid+o]); __syncthreads(); }
    mx = red[0]; __syncthreads();
    float s = 0.f;
    #pragma unroll
    for (int i = 0; i < 4; i++) { v[i] = expf(v[i]-mx); s += v[i]; }
    red[tid] = s; __syncthreads();
    for (int o = 64; o > 0; o >>= 1) { if (tid < o) red[tid] += red[tid+o]; __syncthreads(); }
    float inv = 1.f / red[0];
    #pragma unroll
    for (int i = 0; i < 4; i++) p[tid + i*128] = v[i]*inv;
}

// x_f = x_q + sigmoid(a1)*delta; h = rmsnorm(x_f, ln2)
__global__ void xf_rms_k(const float* __restrict__ xq, const float* __restrict__ delta,
                         const float* __restrict__ a1, const float* __restrict__ ln2,
                         float* __restrict__ xf, float* __restrict__ hout) {
    int m = blockIdx.x;
    int tid = threadIdx.x;  // 256
    float sig = 1.f/(1.f + expf(-a1[0]));
    const size_t base = (size_t)m*DD;
    float vals[8];
    float s = 0.f;
    #pragma unroll
    for (int i = 0; i < 8; i++) {
        int d = tid + i*256;
        float v = xq[base+d] + sig*delta[base+d];
        vals[i] = v; s += v*v;
    }
    __shared__ float red[256];
    red[tid] = s; __syncthreads();
    for (int o = 128; o > 0; o >>= 1) { if (tid < o) red[tid] += red[tid+o]; __syncthreads(); }
    float rr = rsqrtf(red[0] * (1.f/DD) + EPSV);
    #pragma unroll
    for (int i = 0; i < 8; i++) {
        int d = tid + i*256;
        xf[base+d]  = vals[i];
        hout[base+d] = ln2[d] * vals[i] * rr;
    }
}

// T1[m,r] = sum_d H[m,d]*A1[d,r]  (+ optionally T2 with A2); rank 16, 16 warps
__global__ void lora16_k(const float* __restrict__ Hm, const float* __restrict__ A1,
                         const float* __restrict__ A2, float* __restrict__ T1,
                         float* __restrict__ T2, int Kd) {
    extern __shared__ float hrow[];
    int m = blockIdx.x;
    for (int i = threadIdx.x; i < Kd; i += blockDim.x) hrow[i] = Hm[(size_t)m*Kd + i];
    __syncthreads();
    int w = threadIdx.x >> 5, lane = threadIdx.x & 31;
    float s1 = 0.f, s2 = 0.f;
    for (int d = lane; d < Kd; d += 32) {
        float hv = hrow[d];
        s1 += hv * A1[d*RNK + w];
        if (A2) s2 += hv * A2[d*RNK + w];
    }
    #pragma unroll
    for (int o = 16; o > 0; o >>= 1) {
        s1 += __shfl_down_sync(0xffffffffu, s1, o);
        s2 += __shfl_down_sync(0xffffffffu, s2, o);
    }
    if (lane == 0) {
        T1[m*RNK + w] = s1;
        if (A2) T2[m*RNK + w] = s2;
    }
}

// d_in = silu(G + sc*tG@lgB) + (U + sc*tU@luB), written in place over G
__global__ void combine_k(float* __restrict__ G, const float* __restrict__ U,
                          const float* __restrict__ tG, const float* __restrict__ tU,
                          const float* __restrict__ lgB, const float* __restrict__ luB) {
    int m = blockIdx.y;
    int n = blockIdx.x*256 + threadIdx.x;
    __shared__ float sg[RNK], su[RNK];
    if (threadIdx.x < RNK) sg[threadIdx.x] = tG[m*RNK + threadIdx.x];
    else if (threadIdx.x < 2*RNK) su[threadIdx.x - RNK] = tU[m*RNK + threadIdx.x - RNK];
    __syncthreads();
    size_t idx = (size_t)m*INTER + n;
    float g = G[idx], u = U[idx];
    #pragma unroll
    for (int r = 0; r < RNK; r++) {
        g += LORA_SCALE * sg[r] * lgB[r*INTER + n];
        u += LORA_SCALE * su[r] * luB[r*INTER + n];
    }
    float silu = g / (1.f + expf(-g));
    G[idx] = silu + u;
}

// out = x_f + sigmoid(a2)*(mlp + sc*tD@ldB)
__global__ void final_k(const float* __restrict__ xf, const float* __restrict__ mlp,
                        const float* __restrict__ tD, const float* __restrict__ ldB,
                        const float* __restrict__ a2, float* __restrict__ out) {
    int m = blockIdx.y;
    int n = blockIdx.x*256 + threadIdx.x;
    __shared__ float sd[RNK];
    if (threadIdx.x < RNK) sd[threadIdx.x] = tD[m*RNK + threadIdx.x];
    __syncthreads();
    float sig = 1.f/(1.f + expf(-a2[0]));
    size_t idx = (size_t)m*DD + n;
    float r = mlp[idx];
    #pragma unroll
    for (int k = 0; k < RNK; k++) r += LORA_SCALE * sd[k] * ldB[k*DD + n];
    out[idx] = xf[idx] + sig*r;
}

// ---------------- host launch ----------------
extern "C" void kernel_launch(void* const* d_in, const int* in_sizes, int n_in,
                              void* d_out, int out_size) {
    const float* x_q      = (const float*)d_in[0];
    const float* z_a      = (const float*)d_in[1];
    const float* z_v      = (const float*)d_in[2];
    const float* z_av     = (const float*)d_in[3];
    const float* ln1_w    = (const float*)d_in[4];
    const float* ln2_w    = (const float*)d_in[5];
    const float* router_W = (const float*)d_in[6];
    const float* router_b = (const float*)d_in[7];
    const float* Wq       = (const float*)d_in[8];
    const float* bq       = (const float*)d_in[9];
    const float* Wk       = (const float*)d_in[10];
    const float* bk       = (const float*)d_in[11];
    const float* Wv       = (const float*)d_in[12];
    const float* bv       = (const float*)d_in[13];
    const float* Wo       = (const float*)d_in[14];
    const float* bo       = (const float*)d_in[15];
    const float* gate_W   = (const float*)d_in[16];
    const float* up_W     = (const float*)d_in[17];
    const float* down_W   = (const float*)d_in[18];
    const float* lg_A     = (const float*)d_in[19];
    const float* lg_B     = (const float*)d_in[20];
    const float* lu_A     = (const float*)d_in[21];
    const float* lu_B     = (const float*)d_in[22];
    const float* ld_A     = (const float*)d_in[23];
    const float* ld_B     = (const float*)d_in[24];
    const float* alpha_1  = (const float*)d_in[25];
    const float* alpha_2  = (const float*)d_in[26];
    float* out = (float*)d_out;

    float *Qb,*Kb,*Vb,*Sb,*Ob,*Delta,*Xf,*Hb,*Gb,*Ub,*Mlp,*rrms,*qpool,*wattn,*tG,*tU,*tD;
    cudaGetSymbolAddress((void**)&Qb,    g_Q);
    cudaGetSymbolAddress((void**)&Kb,    g_K);
    cudaGetSymbolAddress((void**)&Vb,    g_V);
    cudaGetSymbolAddress((void**)&Sb,    g_S);
    cudaGetSymbolAddress((void**)&Ob,    g_O);
    cudaGetSymbolAddress((void**)&Delta, g_delta);
    cudaGetSymbolAddress((void**)&Xf,    g_xf);
    cudaGetSymbolAddress((void**)&Hb,    g_h);
    cudaGetSymbolAddress((void**)&Gb,    g_G);
    cudaGetSymbolAddress((void**)&Ub,    g_U);
    cudaGetSymbolAddress((void**)&Mlp,   g_mlp);
    cudaGetSymbolAddress((void**)&rrms,  g_rrms);
    cudaGetSymbolAddress((void**)&qpool, g_qpool);
    cudaGetSymbolAddress((void**)&wattn, g_wattn);
    cudaGetSymbolAddress((void**)&tG,    g_tG);
    cudaGetSymbolAddress((void**)&tU,    g_tU);
    cudaGetSymbolAddress((void**)&tD,    g_tD);

    // ---- router ----
    row_rrms_k<<<MQ, 256>>>(x_q, rrms);
    pool_k<<<dim3(DD/256, BB), 256>>>(x_q, rrms, ln1_w, qpool);
    router_k<<<1, 128>>>(qpool, router_W, router_b, wattn);
    zero_k<<<(MQ*DD)/256, 256>>>(Delta, MQ*DD);

    // ---- experts ----
    const float* zs[3] = { z_a, z_v, z_av };
    for (int e = 0; e < NATTN; e++) {
        const float* gate = wattn + e*BB;
        // Q = x_q @ Wq[e] + bq[e]   [4096,2048]
        sgemm_k<false,false,false><<<dim3(DD/128, MQ/128, 1), 256>>>(
            x_q, DD, 0, 0, Wq + (size_t)e*DD*DD, DD, 0, 0,
            Qb, DD, 0, 0, DD, bq + e*DD, 1.f, gate, 1, SQ, 1);
        // K = z_e @ Wk[e] + bk[e]   [2048,2048]
        sgemm_k<false,false,false><<<dim3(DD/128, MKV/128, 1), 256>>>(
            zs[e], KDIM, 0, 0, Wk + (size_t)e*KDIM*DD, DD, 0, 0,
            Kb, DD, 0, 0, KDIM, bk + e*DD, 1.f, gate, 1, SKV, 1);
        // V = z_e @ Wv[e] + bv[e]
        sgemm_k<false,false,false><<<dim3(DD/128, MKV/128, 1), 256>>>(
            zs[e], KDIM, 0, 0, Wv + (size_t)e*KDIM*DD, DD, 0, 0,
            Vb, DD, 0, 0, KDIM, bv + e*DD, 1.f, gate, 1, SKV, 1);
        // scores[b,h] = scale * Q[b,:,h,:] @ K[b,:,h,:]^T   (batched over 64)
        sgemm_k<true,false,false><<<dim3(SKV/128, SQ/128, BB*HH), 256>>>(
            Qb, DD, (long long)SQ*DD, HD,
            Kb, DD, (long long)SKV*DD, HD,
            Sb, SKV, (long long)HH*SQ*SKV, (long long)SQ*SKV,
            HD, nullptr, ATTN_SCALE, gate, HH, 0, HH);
        // softmax
        softmax_k<<<BB*HH*SQ, 128>>>(Sb, gate, HH*SQ);
        // O[b,:,h,:] = P @ V[b,:,h,:]
        sgemm_k<false,false,false><<<dim3(HD/128, SQ/128, BB*HH), 256>>>(
            Sb, SKV, (long long)HH*SQ*SKV, (long long)SQ*SKV,
            Vb, DD, (long long)SKV*DD, HD,
            Ob, DD, (long long)SQ*DD, HD,
            SKV, nullptr, 1.f, gate, HH, 0, HH);
        // delta += w[b,e] * (O @ Wo[e] + bo[e])
        sgemm_k<false,true,true><<<dim3(DD/128, MQ/128, 1), 256>>>(
            Ob, DD, 0, 0, Wo + (size_t)e*DD*DD, DD, 0, 0,
            Delta, DD, 0, 0, DD, bo + e*DD, 1.f, gate, 1, SQ, 1);
    }

    // ---- MLP ----
    xf_rms_k<<<MQ, 256>>>(x_q, Delta, alpha_1, ln2_w, Xf, Hb);
    lora16_k<<<MQ, 512, DD*sizeof(float)>>>(Hb, lg_A, lu_A, tG, tU, DD);
    sgemm_k<false,false,false><<<dim3(INTER/128, MQ/128, 1), 256>>>(
        Hb, DD, 0, 0, gate_W, INTER, 0, 0, Gb, INTER, 0, 0,
        DD, nullptr, 1.f, nullptr, 1, 1, 1);
    sgemm_k<false,false,false><<<dim3(INTER/128, MQ/128, 1), 256>>>(
        Hb, DD, 0, 0, up_W, INTER, 0, 0, Ub, INTER, 0, 0,
        DD, nullptr, 1.f, nullptr, 1, 1, 1);
    combine_k<<<dim3(INTER/256, MQ), 256>>>(Gb, Ub, tG, tU, lg_B, lu_B);
    lora16_k<<<MQ, 512, INTER*sizeof(float)>>>(Gb, ld_A, nullptr, tD, nullptr, INTER);
    sgemm_k<false,false,false><<<dim3(DD/128, MQ/128, 1), 256>>>(
        Gb, INTER, 0, 0, down_W, DD, 0, 0, Mlp, DD, 0, 0,
        INTER, nullptr, 1.f, nullptr, 1, 1, 1);
    final_k<<<dim3(DD/256, MQ), 256>>>(Xf, Mlp, tD, ld_B, alpha_2, out);
}